// round 3
// baseline (speedup 1.0000x reference)
#include <cuda_runtime.h>
#include <cuda_bf16.h>

#define N_NODES  50000
#define HID      128
#define EH       64
#define E_TOTAL  800000
#define N_LAYERS 4

// Persistent scratch (allowed: __device__ globals, no runtime alloc)
__device__ __align__(256) float g_h[N_NODES * HID];     // 25.6 MB, node features
__device__ __align__(256) float g_agg[N_NODES * EH];    // 12.8 MB, message accumulators

__device__ __forceinline__ float silu_f(float x) {
    return x * (1.0f / (1.0f + __expf(-x)));
}

// Vectorized global float4 reduction (sm_90+)
__device__ __forceinline__ void red_add_v4(float* p, float4 v) {
    asm volatile("red.global.add.v4.f32 [%0], {%1,%2,%3,%4};"
                 :: "l"(p), "f"(v.x), "f"(v.y), "f"(v.z), "f"(v.w) : "memory");
}

#define FMA16(A4, B4, ACC) do { \
    ACC[0][0] += A4.x*B4.x; ACC[0][1] += A4.x*B4.y; ACC[0][2] += A4.x*B4.z; ACC[0][3] += A4.x*B4.w; \
    ACC[1][0] += A4.y*B4.x; ACC[1][1] += A4.y*B4.y; ACC[1][2] += A4.y*B4.z; ACC[1][3] += A4.y*B4.w; \
    ACC[2][0] += A4.z*B4.x; ACC[2][1] += A4.z*B4.y; ACC[2][2] += A4.z*B4.z; ACC[2][3] += A4.z*B4.w; \
    ACC[3][0] += A4.w*B4.x; ACC[3][1] += A4.w*B4.y; ACC[3][2] += A4.w*B4.z; ACC[3][3] += A4.w*B4.w; \
} while(0)

// ---------------------------------------------------------------------------
// zero g_agg : exactly 800000 float4 = 50000*64 floats
__global__ void zero_agg_kernel() {
    int i = blockIdx.x * blockDim.x + threadIdx.x;
    ((float4*)g_agg)[i] = make_float4(0.f, 0.f, 0.f, 0.f);
}

// ---------------------------------------------------------------------------
// emb_in: g_h[N,128] = x[N,64] @ W[64,128] + b
// block: 32 nodes x 128 cols, 256 threads, thread tile 4x4 (tx: col grp, ty: node grp)
__global__ void __launch_bounds__(256) emb_in_kernel(
    const float* __restrict__ x, const float* __restrict__ W, const float* __restrict__ b)
{
    __shared__ float As[64 * 36];   // k-major, stride 36 (pad)
    __shared__ float Bs[64 * 128];
    int tid = threadIdx.x;
    int tx = tid & 31, ty = tid >> 5;
    int n0 = blockIdx.x * 32;

    { // gather A (coalesced rows, transposed store)
        int n = tid >> 3, kk = tid & 7;
        int node = n0 + n;
        #pragma unroll
        for (int it = 0; it < 2; it++) {
            int k4 = kk + it * 8;                     // 0..15 float4 along K=64
            float4 v = make_float4(0.f, 0.f, 0.f, 0.f);
            if (node < N_NODES) v = ((const float4*)(x + node * 64))[k4];
            As[(k4*4+0)*36 + n] = v.x; As[(k4*4+1)*36 + n] = v.y;
            As[(k4*4+2)*36 + n] = v.z; As[(k4*4+3)*36 + n] = v.w;
        }
    }
    { // W [64][128] -> Bs
        const float4* wp = (const float4*)W;
        float4* bp = (float4*)Bs;
        #pragma unroll
        for (int it = 0; it < 8; it++) bp[tid + it * 256] = wp[tid + it * 256];
    }
    __syncthreads();

    float acc[4][4] = {};
    #pragma unroll
    for (int k = 0; k < 64; k++) {
        float4 a  = *(const float4*)(As + k * 36 + ty * 4);
        float4 bb = *(const float4*)(Bs + k * 128 + tx * 4);
        FMA16(a, bb, acc);
    }
    float4 bias = *(const float4*)(b + tx * 4);
    #pragma unroll
    for (int i = 0; i < 4; i++) {
        int node = n0 + ty * 4 + i;
        if (node < N_NODES) {
            float4 v = make_float4(acc[i][0]+bias.x, acc[i][1]+bias.y,
                                   acc[i][2]+bias.z, acc[i][3]+bias.w);
            *((float4*)(g_h + node * 128) + tx) = v;
        }
    }
}

// ---------------------------------------------------------------------------
// edge kernel: per block, 64 edges. feat=[h[row],h[col]] (K=256)
//   m1 = silu(feat @ W1 + b1)  [64 x 64]
//   m2 = silu(m1  @ W2 + b2)   [64 x 64]
//   red-add m2 into g_agg[row]
// threads: 256, tx = col grp (16x4), ty = edge grp (16x4)
__global__ void __launch_bounds__(256) edge_kernel(
    const int* __restrict__ erow, const int* __restrict__ ecol,
    const float* __restrict__ W1, const float* __restrict__ b1,
    const float* __restrict__ W2, const float* __restrict__ b2)
{
    __shared__ int   sSrc[2][64];
    __shared__ float AstBuf[64 * 68];   // k-major A chunk (pad 68); reused as Ms[64][64]
    __shared__ float Bs[64 * 64];
    int tid = threadIdx.x;
    int tx = tid & 15, ty = tid >> 4;
    int e0 = blockIdx.x * 64;

    if (tid < 64)        sSrc[0][tid]      = erow[e0 + tid];
    else if (tid < 128)  sSrc[1][tid - 64] = ecol[e0 + tid - 64];
    __syncthreads();

    float acc[4][4] = {};
    #pragma unroll
    for (int ch = 0; ch < 4; ch++) {       // K chunks: row[0:64],row[64:128],col[0:64],col[64:128]
        if (ch) __syncthreads();
        { // gather A chunk -> k-major smem
            int e = tid >> 2, kk = tid & 3;
            int src = sSrc[ch >> 1][e];
            const float4* hp = (const float4*)(g_h + src * 128 + (ch & 1) * 64);
            #pragma unroll
            for (int it = 0; it < 4; it++) {
                int k4 = kk + it * 4;               // 0..15
                float4 v = hp[k4];
                AstBuf[(k4*4+0)*68 + e] = v.x; AstBuf[(k4*4+1)*68 + e] = v.y;
                AstBuf[(k4*4+2)*68 + e] = v.z; AstBuf[(k4*4+3)*68 + e] = v.w;
            }
        }
        { // W1 chunk [64][64]
            const float4* wp = (const float4*)(W1 + ch * 4096);
            float4* bp = (float4*)Bs;
            #pragma unroll
            for (int it = 0; it < 4; it++) bp[tid + it * 256] = wp[tid + it * 256];
        }
        __syncthreads();
        #pragma unroll
        for (int k = 0; k < 64; k++) {
            float4 a  = *(const float4*)(AstBuf + k * 68 + ty * 4);
            float4 bb = *(const float4*)(Bs + k * 64 + tx * 4);
            FMA16(a, bb, acc);
        }
    }

    // epilogue 1: bias + silu -> Ms (e-major), reuse AstBuf
    float4 bias1 = *(const float4*)(b1 + tx * 4);
    __syncthreads();                       // all GEMM1 smem reads done
    float* Ms = AstBuf;
    #pragma unroll
    for (int i = 0; i < 4; i++) {
        float4 v;
        v.x = silu_f(acc[i][0] + bias1.x);
        v.y = silu_f(acc[i][1] + bias1.y);
        v.z = silu_f(acc[i][2] + bias1.z);
        v.w = silu_f(acc[i][3] + bias1.w);
        *(float4*)(Ms + (ty * 4 + i) * 64 + tx * 4) = v;
    }
    { // W2 [64][64]
        const float4* wp = (const float4*)W2;
        float4* bp = (float4*)Bs;
        #pragma unroll
        for (int it = 0; it < 4; it++) bp[tid + it * 256] = wp[tid + it * 256];
    }
    __syncthreads();

    float acc2[4][4] = {};
    #pragma unroll
    for (int k = 0; k < 64; k++) {
        float4 bb = *(const float4*)(Bs + k * 64 + tx * 4);
        #pragma unroll
        for (int i = 0; i < 4; i++) {
            float a = Ms[(ty * 4 + i) * 64 + k];
            acc2[i][0] += a * bb.x; acc2[i][1] += a * bb.y;
            acc2[i][2] += a * bb.z; acc2[i][3] += a * bb.w;
        }
    }

    float4 bias2 = *(const float4*)(b2 + tx * 4);
    #pragma unroll
    for (int i = 0; i < 4; i++) {
        int r = sSrc[0][ty * 4 + i];
        float4 v;
        v.x = silu_f(acc2[i][0] + bias2.x);
        v.y = silu_f(acc2[i][1] + bias2.y);
        v.z = silu_f(acc2[i][2] + bias2.z);
        v.w = silu_f(acc2[i][3] + bias2.w);
        red_add_v4(g_agg + r * 64 + tx * 4, v);
    }
}

// ---------------------------------------------------------------------------
// node kernel: upd = silu([h, C*agg] @ W1 + b1) @ W2 + b2 ; if mask: h += upd
// block: 32 nodes x 128 cols, 256 threads (tx: col grp 32x4, ty: node grp 8x4)
// dynamic smem: As[64*36] + Bs[64*128] + Ts[32*128]
// mask: int32 (JAX bool materialized as int32 by the harness)
__global__ void __launch_bounds__(256) node_kernel(
    const float* __restrict__ W1, const float* __restrict__ b1,
    const float* __restrict__ W2, const float* __restrict__ b2,
    const int* __restrict__ mask, float C)
{
    extern __shared__ float sm[];
    float* As = sm;                 // 64*36
    float* Bs = sm + 64 * 36;       // 64*128
    float* Ts = Bs + 64 * 128;      // 32*128
    int tid = threadIdx.x;
    int tx = tid & 31, ty = tid >> 5;
    int n0 = blockIdx.x * 32;

    float acc[4][4] = {};
    #pragma unroll
    for (int ch = 0; ch < 3; ch++) {        // K=192: h[0:64], h[64:128], C*agg[0:64]
        __syncthreads();
        {
            int n = tid >> 3, kk = tid & 7;
            int node = n0 + n;
            #pragma unroll
            for (int it = 0; it < 2; it++) {
                int k4 = kk + it * 8;       // 0..15
                float4 v = make_float4(0.f, 0.f, 0.f, 0.f);
                if (node < N_NODES) {
                    if (ch < 2) v = ((const float4*)(g_h + node * 128 + ch * 64))[k4];
                    else {
                        v = ((const float4*)(g_agg + node * 64))[k4];
                        v.x *= C; v.y *= C; v.z *= C; v.w *= C;
                    }
                }
                As[(k4*4+0)*36 + n] = v.x; As[(k4*4+1)*36 + n] = v.y;
                As[(k4*4+2)*36 + n] = v.z; As[(k4*4+3)*36 + n] = v.w;
            }
        }
        { // W1 chunk [64][128]
            const float4* wp = (const float4*)(W1 + ch * 64 * 128);
            float4* bp = (float4*)Bs;
            #pragma unroll
            for (int it = 0; it < 8; it++) bp[tid + it * 256] = wp[tid + it * 256];
        }
        __syncthreads();
        #pragma unroll
        for (int k = 0; k < 64; k++) {
            float4 a  = *(const float4*)(As + k * 36 + ty * 4);
            float4 bb = *(const float4*)(Bs + k * 128 + tx * 4);
            FMA16(a, bb, acc);
        }
    }

    // epilogue 1: bias + silu -> Ts (node-major)
    float4 bias1 = *(const float4*)(b1 + tx * 4);
    #pragma unroll
    for (int i = 0; i < 4; i++) {
        float4 v;
        v.x = silu_f(acc[i][0] + bias1.x);
        v.y = silu_f(acc[i][1] + bias1.y);
        v.z = silu_f(acc[i][2] + bias1.z);
        v.w = silu_f(acc[i][3] + bias1.w);
        *(float4*)(Ts + (ty * 4 + i) * 128 + tx * 4) = v;
    }

    float acc2[4][4] = {};
    #pragma unroll
    for (int ch = 0; ch < 2; ch++) {        // K=128
        __syncthreads();                    // Ts visible / Bs free
        {
            const float4* wp = (const float4*)(W2 + ch * 64 * 128);
            float4* bp = (float4*)Bs;
            #pragma unroll
            for (int it = 0; it < 8; it++) bp[tid + it * 256] = wp[tid + it * 256];
        }
        __syncthreads();
        #pragma unroll
        for (int k = 0; k < 64; k++) {
            float4 bb = *(const float4*)(Bs + k * 128 + tx * 4);
            #pragma unroll
            for (int i = 0; i < 4; i++) {
                float a = Ts[(ty * 4 + i) * 128 + ch * 64 + k];
                acc2[i][0] += a * bb.x; acc2[i][1] += a * bb.y;
                acc2[i][2] += a * bb.z; acc2[i][3] += a * bb.w;
            }
        }
    }

    float4 bias2 = *(const float4*)(b2 + tx * 4);
    #pragma unroll
    for (int i = 0; i < 4; i++) {
        int node = n0 + ty * 4 + i;
        if (node < N_NODES && mask[node] != 0) {
            float4* hp = (float4*)(g_h + node * 128) + tx;
            float4 o = *hp;
            o.x += acc2[i][0] + bias2.x;
            o.y += acc2[i][1] + bias2.y;
            o.z += acc2[i][2] + bias2.z;
            o.w += acc2[i][3] + bias2.w;
            *hp = o;
        }
    }
}

// ---------------------------------------------------------------------------
// emb_out: out[N,64] = g_h[N,128] @ W[128,64] + b
// block: 64 nodes x 64 cols, 256 threads (tx 16x4 cols, ty 16x4 nodes), K=128 (2 chunks)
__global__ void __launch_bounds__(256) emb_out_kernel(
    const float* __restrict__ W, const float* __restrict__ b, float* __restrict__ out)
{
    __shared__ float As[64 * 68];
    __shared__ float Bs[64 * 64];
    int tid = threadIdx.x;
    int tx = tid & 15, ty = tid >> 4;
    int n0 = blockIdx.x * 64;

    float acc[4][4] = {};
    #pragma unroll
    for (int ch = 0; ch < 2; ch++) {
        if (ch) __syncthreads();
        {
            int n = tid >> 2, kk = tid & 3;
            int node = n0 + n;
            #pragma unroll
            for (int it = 0; it < 4; it++) {
                int k4 = kk + it * 4;
                float4 v = make_float4(0.f, 0.f, 0.f, 0.f);
                if (node < N_NODES) v = ((const float4*)(g_h + node * 128 + ch * 64))[k4];
                As[(k4*4+0)*68 + n] = v.x; As[(k4*4+1)*68 + n] = v.y;
                As[(k4*4+2)*68 + n] = v.z; As[(k4*4+3)*68 + n] = v.w;
            }
        }
        {
            const float4* wp = (const float4*)(W + ch * 64 * 64);
            float4* bp = (float4*)Bs;
            #pragma unroll
            for (int it = 0; it < 4; it++) bp[tid + it * 256] = wp[tid + it * 256];
        }
        __syncthreads();
        #pragma unroll
        for (int k = 0; k < 64; k++) {
            float4 a  = *(const float4*)(As + k * 68 + ty * 4);
            float4 bb = *(const float4*)(Bs + k * 64 + tx * 4);
            FMA16(a, bb, acc);
        }
    }
    float4 bias = *(const float4*)(b + tx * 4);
    #pragma unroll
    for (int i = 0; i < 4; i++) {
        int node = n0 + ty * 4 + i;
        if (node < N_NODES) {
            float4 v = make_float4(acc[i][0]+bias.x, acc[i][1]+bias.y,
                                   acc[i][2]+bias.z, acc[i][3]+bias.w);
            *((float4*)(out + node * 64) + tx) = v;
        }
    }
}

// ---------------------------------------------------------------------------
extern "C" void kernel_launch(void* const* d_in, const int* in_sizes, int n_in,
                              void* d_out, int out_size)
{
    (void)in_sizes; (void)n_in; (void)out_size;
    const float* h0     = (const float*)d_in[0];
    const int*   ea     = (const int*)d_in[1];      // [2, E]
    const int*   ebp    = (const int*)d_in[2];      // [2, E]
    const int*   ma     = (const int*)d_in[3];      // bool -> int32
    const int*   mb     = (const int*)d_in[4];      // bool -> int32
    const float* w_in   = (const float*)d_in[5];
    const float* b_in   = (const float*)d_in[6];
    const float* w_out  = (const float*)d_in[7];
    const float* b_out  = (const float*)d_in[8];
    const float* ew1    = (const float*)d_in[9];    // [4,256,64]
    const float* eb1    = (const float*)d_in[10];   // [4,64]
    const float* ew2    = (const float*)d_in[11];   // [4,64,64]
    const float* eb2    = (const float*)d_in[12];   // [4,64]
    const float* nw1    = (const float*)d_in[13];   // [4,192,128]
    const float* nb1    = (const float*)d_in[14];   // [4,128]
    const float* nw2    = (const float*)d_in[15];   // [4,128,128]
    const float* nb2    = (const float*)d_in[16];   // [4,128]
    float*       out    = (float*)d_out;

    const int NODE_SMEM = (64 * 36 + 64 * 128 + 32 * 128) * (int)sizeof(float); // 58368
    (void)cudaFuncSetAttribute(node_kernel, cudaFuncAttributeMaxDynamicSharedMemorySize, NODE_SMEM);

    emb_in_kernel<<<(N_NODES + 31) / 32, 256>>>(h0, w_in, b_in);

    for (int l = 0; l < N_LAYERS; l++) {
        const int* er = (l & 1) ? ebp : ea;
        const int* m  = (l & 1) ? mb : ma;
        float C = (l & 1) ? (2.0f / 64.0f) : 1.0f;

        zero_agg_kernel<<<(N_NODES * EH / 4) / 256, 256>>>();
        edge_kernel<<<E_TOTAL / 64, 256>>>(er, er + E_TOTAL,
                                           ew1 + l * 256 * 64, eb1 + l * 64,
                                           ew2 + l * 64 * 64,  eb2 + l * 64);
        node_kernel<<<(N_NODES + 31) / 32, 256, NODE_SMEM>>>(
            nw1 + l * 192 * 128, nb1 + l * 128,
            nw2 + l * 128 * 128, nb2 + l * 128, m, C);
    }

    emb_out_kernel<<<(N_NODES + 63) / 64, 256>>>(w_out, b_out, out);
}